// round 14
// baseline (speedup 1.0000x reference)
#include <cuda_runtime.h>
#include <cuda_bf16.h>
#include <cstdint>

#define B_    512
#define H_    1024
#define NE    4096
#define ND    4352
#define KBE   2304      // Benc2 physical cols: Whi|Wlo|Wi_hi(128)|Wi_lo(128)
#define KBD   2176      // Bdec2 physical cols: Whi|Wlo|Wi_hi(64)|Wi_lo(64)
#define KTE   3456      // logical K enc
#define KTD   3264      // logical K dec

// ----------------------- device scratch (no allocs) ------------------------
__device__ __nv_bfloat16 g_Benc2[(size_t)NE * KBE];
__device__ __nv_bfloat16 g_Bdec2[(size_t)ND * KBD];
__device__ __nv_bfloat16 g_xenc2[(size_t)128 * B_ * 256];
__device__ __nv_bfloat16 g_ftp2[(size_t)32 * B_ * 128];
__device__ __nv_bfloat16 g_hP2[2][(size_t)B_ * 2048];        // parity, hi|lo
__device__ float         g_h[2][(size_t)B_ * H_];
__device__ float         g_Wc[(size_t)3072 * H_];
__device__ float         g_wob[3072];

__device__ __forceinline__ __nv_bfloat16 split_val(float w, bool lo) {
    __nv_bfloat16 hi = __float2bfloat16(w);
    if (!lo) return hi;
    return __float2bfloat16(w - __bfloat162float(hi));
}

// ------------------------------ precompute ---------------------------------
__global__ void k_wc(const float* __restrict__ Wi, const float* __restrict__ Wd) {
    int idx = blockIdx.x * 256 + threadIdx.x;          // exact 3072*1024
    int n = idx >> 10, k = idx & 1023;
    const float* wrow = Wi + n * 128 + 64;
    float s = 0.f;
#pragma unroll 8
    for (int o = 0; o < 64; o++) s += wrow[o] * Wd[o * 1024 + k];
    g_Wc[idx] = s;
}

__global__ void k_wob(const float* __restrict__ Wi, const float* __restrict__ bd) {
    int n = blockIdx.x * 256 + threadIdx.x;
    if (n >= 3072) return;
    float s = 0.f;
#pragma unroll 8
    for (int o = 0; o < 64; o++) s += Wi[n * 128 + 64 + o] * bd[o];
    g_wob[n] = s;
}

// Benc2 rows: [0,1024)=r ; [1024,2048)=z ; [2048,3072)=n_h ; [3072,4096)=n_i
// cols: [0,1024) W-hi | [1024,2048) W-lo | [2048,2176) Wi-hi | [2176,2304) Wi-lo
__global__ void build_benc2(const float* __restrict__ Wi, const float* __restrict__ Wh) {
    size_t idx = (size_t)blockIdx.x * 256 + threadIdx.x;   // exact NE*KBE
    int p = (int)(idx / KBE);
    int c = (int)(idx - (size_t)p * KBE);
    float w = 0.f; bool lo = false;
    if (c < 2048) {
        int cc = c & 1023; lo = (c >= 1024);
        if (p < 3072) w = Wh[(size_t)p * 1024 + cc];
    } else {
        int q = c - 2048; lo = (q >= 128); q &= 127;
        if (p < 2048)       w = Wi[p * 128 + q];
        else if (p >= 3072) w = Wi[(p - 1024) * 128 + q];
    }
    g_Benc2[idx] = split_val(w, lo);
}

// Bdec2 rows: [0,2048)=r,z (Wh+Wc) ; [2048,3072)=n_h (Wh) ; [3072,4096)=n_i (Wc)
//             [4096,4160)=Wd ; rest 0.
// cols: [0,1024) W-hi | [1024,2048) W-lo | [2048,2112) Wi-hi | [2112,2176) Wi-lo
__global__ void build_bdec2(const float* __restrict__ Wi, const float* __restrict__ Wh,
                            const float* __restrict__ Wd) {
    size_t idx = (size_t)blockIdx.x * 256 + threadIdx.x;   // exact ND*KBD
    int p = (int)(idx / KBD);
    int c = (int)(idx - (size_t)p * KBD);
    float w = 0.f; bool lo = false;
    if (c < 2048) {
        int cc = c & 1023; lo = (c >= 1024);
        if (p < 2048)      w = Wh[(size_t)p * 1024 + cc] + g_Wc[(size_t)p * 1024 + cc];
        else if (p < 3072) w = Wh[(size_t)p * 1024 + cc];
        else if (p < 4096) w = g_Wc[(size_t)(p - 1024) * 1024 + cc];
        else if (p < 4160) w = Wd[(size_t)(p - 4096) * 1024 + cc];
    } else {
        int q = c - 2048; lo = (q >= 64); q &= 63;
        if (p < 2048)                      w = Wi[p * 128 + q];
        else if (p >= 3072 && p < 4096)    w = Wi[(p - 1024) * 128 + q];
    }
    g_Bdec2[idx] = split_val(w, lo);
}

// xenc2[t][m][c]: c<128 hi of x, c>=128 lo ; x = [prior_t | labels_t]
__global__ void k_xenc2(const float* __restrict__ feats, const float* __restrict__ labels) {
    size_t idx = (size_t)blockIdx.x * 256 + threadIdx.x;   // exact 128*B_*256
    int t = (int)(idx / ((size_t)B_ * 256));
    int rem = (int)(idx - (size_t)t * B_ * 256);
    int m = rem >> 8;
    int c = rem & 255;
    int kk = c & 127;
    float v = (kk < 64) ? feats[((size_t)m * 159 + t) * 64 + kk]
                        : labels[((size_t)m * 128 + t) * 64 + (kk - 64)];
    g_xenc2[idx] = split_val(v, c >= 128);
}

// ftp2[j][m][c]: c<64 hi, c>=64 lo ; slot 31 zero
__global__ void k_ftp2(const float* __restrict__ feats) {
    size_t idx = (size_t)blockIdx.x * 256 + threadIdx.x;   // exact 32*B_*128
    int j = (int)(idx / ((size_t)B_ * 128));
    int rem = (int)(idx - (size_t)j * B_ * 128);
    int m = rem >> 7;
    int c = rem & 127;
    float v = (j == 31) ? 0.f : feats[((size_t)m * 159 + 128 + j) * 64 + (c & 63)];
    g_ftp2[idx] = split_val(v, c >= 64);
}

__global__ void init_h() {
    int idx = blockIdx.x * 256 + threadIdx.x;              // exact B_*2048
    g_hP2[0][idx] = __float2bfloat16(0.f);
    if (idx < B_ * H_) g_h[0][idx] = 0.f;
}

// --------------------------- mma helpers -----------------------------------
__device__ __forceinline__ void ldsm4(unsigned& r0, unsigned& r1, unsigned& r2,
                                      unsigned& r3, const void* p) {
    unsigned a = (unsigned)__cvta_generic_to_shared(p);
    asm volatile("ldmatrix.sync.aligned.m8n8.x4.shared.b16 {%0,%1,%2,%3},[%4];"
                 : "=r"(r0), "=r"(r1), "=r"(r2), "=r"(r3) : "r"(a));
}

__device__ __forceinline__ void mma16816(float* c, const unsigned* a,
                                         unsigned b0, unsigned b1) {
    asm volatile(
        "mma.sync.aligned.m16n8k16.row.col.f32.bf16.bf16.f32 "
        "{%0,%1,%2,%3},{%4,%5,%6,%7},{%8,%9},{%0,%1,%2,%3};"
        : "+f"(c[0]), "+f"(c[1]), "+f"(c[2]), "+f"(c[3])
        : "r"(a[0]), "r"(a[1]), "r"(a[2]), "r"(a[3]), "r"(b0), "r"(b1));
}

__device__ __forceinline__ void cpa16(uint32_t dst, const void* src) {
    asm volatile("cp.async.cg.shared.global [%0], [%1], 16;" :: "r"(dst), "l"(src));
}
#define CP_COMMIT() asm volatile("cp.async.commit_group;" ::: "memory")
#define CP_WAIT2()  asm volatile("cp.async.wait_group 2;" ::: "memory")

// ------------------------------ fused step ---------------------------------
// Gate CTA: 64(M) x 64(N-per-gate). Encoder: 3 B strips (r, z, nh|ni shared).
// Decoder: 4 B strips (r, z, nh, ni — ni carries Wc*h, the folded ps feedback).
// Epilogue does the GRU pointwise in registers. ps CTA (cid>=128): Wd readout.
// Stage: A 64x144B + B 256x144B = 46080B; 4 stages, depth-3 prefetch.
#define KC     64
#define ROWB   144
#define STGB   46080
#define SMEMD  (4 * STGB)

__global__ __launch_bounds__(256)
void gru_step(int mode, int step, int parity, int base,
              const float* __restrict__ bi, const float* __restrict__ bh,
              const float* __restrict__ bd, float* __restrict__ out) {
    extern __shared__ char dsm[];
    const int cid = blockIdx.x + base;
    const bool psk = (cid >= 128);
    const int tid = threadIdx.x, lane = tid & 31, wid = tid >> 5;
    const int ncol = psk ? 0 : (cid & 15);
    const int mtile = psk ? (cid - 128) : (cid >> 4);
    const int m0 = mtile * 64;
    const int nstrips = psk ? 1 : (mode ? 4 : 3);
    const uint32_t sb = (unsigned)__cvta_generic_to_shared(dsm);

    int KB, lda2;
    const __nv_bfloat16 *Bmat, *A2;
    if (mode == 0) { KB = KBE; Bmat = g_Benc2; A2 = g_xenc2 + (size_t)step * B_ * 256; lda2 = 256; }
    else           { KB = KBD; Bmat = g_Bdec2; A2 = g_ftp2  + (size_t)step * B_ * 128; lda2 = 128; }
    const int nch = mode ? 51 : 54;
    const __nv_bfloat16* hPrd = g_hP2[parity];
    const int iters = psk ? 4 : (mode ? 10 : 8);
    const int nbch = nstrips * 512;          // B cp.async chunks per stage

    auto FILL = [&](int f) {
        int kb = f * KC;
        uint32_t bbase = sb + (f & 3) * STGB;
        const __nv_bfloat16* asrc; int lda, kc;
        if (kb < 2048)      { asrc = hPrd; lda = 2048; kc = kb; }
        else if (kb < 3072) { asrc = hPrd; lda = 2048; kc = kb - 2048; }
        else {
            asrc = A2; lda = lda2;
            if (mode == 0) kc = (kb < 3328) ? kb - 3072 : kb - 3328;
            else           kc = (kb < 3200) ? kb - 3072 : kb - 3200;
        }
        int bc;
        if (mode == 0) bc = (kb < 1024) ? kb : ((kb < 3200) ? kb - 1024 : kb - 1152);
        else           bc = (kb < 1024) ? kb : ((kb < 3136) ? kb - 1024 : kb - 1088);
        const int rb2 = (kb < 3072) ? 2048 : 3072;   // encoder strip-2 row base
        for (int it = 0; it < iters; it++) {
            int ch = tid + it * 256;
            if (ch < 512) {
                int row = ch >> 3, seg = ch & 7;
                cpa16(bbase + row * ROWB + seg * 16,
                      (const char*)(asrc + (size_t)(m0 + row) * lda + kc) + seg * 16);
            } else if (ch < 512 + nbch) {
                int g = ch - 512;
                int brow = g >> 3, seg = g & 7;
                int s = brow >> 6, r = brow & 63;
                int p;
                if (psk)           p = 4096 + r;
                else if (s == 0)   p = ncol * 64 + r;
                else if (s == 1)   p = 1024 + ncol * 64 + r;
                else if (s == 2)   p = (mode ? 2048 : rb2) + ncol * 64 + r;
                else               p = 3072 + ncol * 64 + r;       // decoder n_i
                cpa16(bbase + 9216 + brow * ROWB + seg * 16,
                      (const char*)(Bmat + (size_t)p * KB + bc) + seg * 16);
            }
        }
        CP_COMMIT();
    };

    const int wm = (wid & 1) * 32;       // 2 warps over M (64)
    const int wn = (wid >> 1) * 16;      // 4 warps over N (64)
    const int grp = lane >> 2, tig = lane & 3;

    float acc[4][2][2][4];
#pragma unroll
    for (int g = 0; g < 4; g++)
#pragma unroll
        for (int mi = 0; mi < 2; mi++)
#pragma unroll
            for (int nj = 0; nj < 2; nj++)
#pragma unroll
                for (int q = 0; q < 4; q++) acc[g][mi][nj][q] = 0.f;

    FILL(0); FILL(1); FILL(2);

    for (int i = 0; i < nch; i++) {
        CP_WAIT2();
        __syncthreads();
        __nv_bfloat16* As = (__nv_bfloat16*)(dsm + (i & 3) * STGB);
        __nv_bfloat16* Bs = As + 64 * 72;
        const int g2 = (mode || psk) ? 2 : ((i * KC < 3072) ? 2 : 3);

#pragma unroll
        for (int kh = 0; kh < 64; kh += 16) {
            unsigned a[2][4], b[4][4];
#pragma unroll
            for (int mi = 0; mi < 2; mi++)
                ldsm4(a[mi][0], a[mi][1], a[mi][2], a[mi][3],
                      As + (wm + mi * 16 + (lane & 15)) * 72 + kh + (lane >> 4) * 8);
#pragma unroll
            for (int s = 0; s < 4; s++)
                if (s < nstrips)
                    ldsm4(b[s][0], b[s][1], b[s][2], b[s][3],
                          Bs + (s * 64 + wn + (lane & 15)) * 72 + kh + (lane >> 4) * 8);
#pragma unroll
            for (int s = 0; s < 4; s++) {
                if (s >= nstrips) continue;
                int g = (s == 2) ? g2 : s;
#pragma unroll
                for (int mi = 0; mi < 2; mi++)
#pragma unroll
                    for (int nj = 0; nj < 2; nj++)
                        mma16816(acc[g][mi][nj], a[mi],
                                 b[s][nj], b[s][nj + 2]);
            }
        }
        int f = i + 3;
        if (f < nch) FILL(f); else CP_COMMIT();
    }

    // ------------------------------ epilogue -------------------------------
    if (psk) {
        float* o = out;
#pragma unroll
        for (int mi = 0; mi < 2; mi++)
#pragma unroll
            for (int half = 0; half < 2; half++) {
                int row = m0 + wm + mi * 16 + grp + half * 8;
#pragma unroll
                for (int nj = 0; nj < 2; nj++) {
                    int col = wn + nj * 8 + tig * 2;
                    float2 v;
                    v.x = acc[0][mi][nj][half * 2 + 0] + bd[col];
                    v.y = acc[0][mi][nj][half * 2 + 1] + bd[col + 1];
                    *(float2*)&o[(size_t)row * 64 + col] = v;
                }
            }
        return;
    }

    const int pw = parity ^ 1;
    const float* hr = g_h[parity];
    float* hw = g_h[pw];
    __nv_bfloat16* hPw = g_hP2[pw];

#pragma unroll
    for (int mi = 0; mi < 2; mi++)
#pragma unroll
        for (int half = 0; half < 2; half++) {
            int row = m0 + wm + mi * 16 + grp + half * 8;
#pragma unroll
            for (int nj = 0; nj < 2; nj++) {
#pragma unroll
                for (int c = 0; c < 2; c++) {
                    int coln = wn + nj * 8 + tig * 2 + c;
                    int n = ncol * 64 + coln;
                    int q = half * 2 + c;
                    float wr = mode ? g_wob[n] : 0.f;
                    float wz = mode ? g_wob[1024 + n] : 0.f;
                    float wn_ = mode ? g_wob[2048 + n] : 0.f;
                    float r = acc[0][mi][nj][q] + bi[n] + bh[n] + wr;
                    float z = acc[1][mi][nj][q] + bi[1024 + n] + bh[1024 + n] + wz;
                    float ghn = acc[2][mi][nj][q] + bh[2048 + n];
                    float gin = acc[3][mi][nj][q] + bi[2048 + n] + wn_;
                    r = 1.f / (1.f + __expf(-r));
                    z = 1.f / (1.f + __expf(-z));
                    float nn = tanhf(gin + r * ghn);
                    float ho = hr[(size_t)row * 1024 + n];
                    float h = (1.f - z) * nn + z * ho;
                    hw[(size_t)row * 1024 + n] = h;
                    __nv_bfloat16 hi = __float2bfloat16(h);
                    __nv_bfloat16 lo = __float2bfloat16(h - __bfloat162float(hi));
                    hPw[(size_t)row * 2048 + n] = hi;
                    hPw[(size_t)row * 2048 + 1024 + n] = lo;
                }
            }
        }
}

// ------------------------------- launch ------------------------------------
extern "C" void kernel_launch(void* const* d_in, const int* in_sizes, int n_in,
                              void* d_out, int out_size) {
    const float* feats  = (const float*)d_in[0];
    const float* labels = (const float*)d_in[1];
    const float* Wi     = (const float*)d_in[2];
    const float* Wh     = (const float*)d_in[3];
    const float* bi     = (const float*)d_in[4];
    const float* bh     = (const float*)d_in[5];
    const float* Wd     = (const float*)d_in[6];
    const float* bd     = (const float*)d_in[7];
    float* out = (float*)d_out;

    cudaFuncSetAttribute(gru_step, cudaFuncAttributeMaxDynamicSharedMemorySize,
                         SMEMD);

    k_wc<<<12288, 256>>>(Wi, Wd);
    k_wob<<<12, 256>>>(Wi, bd);
    build_benc2<<<(int)(((size_t)NE * KBE) / 256), 256>>>(Wi, Wh);
    build_bdec2<<<(int)(((size_t)ND * KBD) / 256), 256>>>(Wi, Wh, Wd);
    k_xenc2<<<(int)(((size_t)128 * B_ * 256) / 256), 256>>>(feats, labels);
    k_ftp2<<<(int)(((size_t)32 * B_ * 128) / 256), 256>>>(feats);
    init_h<<<(B_ * 2048) / 256, 256>>>();

    for (int t = 0; t < 128; t++)
        gru_step<<<128, 256, SMEMD>>>(0, t, t & 1, 0, bi, bh, bd, out);
    for (int j = 0; j < 31; j++)
        gru_step<<<136, 256, SMEMD>>>(1, j, j & 1, 0, bi, bh, bd,
                                      out + (size_t)j * B_ * 64);
    gru_step<<<8, 256, SMEMD>>>(1, 31, 1, 128, bi, bh, bd,
                                out + (size_t)31 * B_ * 64);
}

// round 16
// speedup vs baseline: 3.8768x; 3.8768x over previous
#include <cuda_runtime.h>
#include <cuda_bf16.h>
#include <cstdint>

#define B_    512
#define H_    1024
#define NE    4096
#define ND    4352
#define KBE   2304      // Benc2 physical cols: Whi|Wlo|Wi_hi(128)|Wi_lo(128)
#define KBD   2176      // Bdec2 physical cols: Whi|Wlo|Wi_hi(64)|Wi_lo(64)

// ----------------------- device scratch (no allocs) ------------------------
__device__ __nv_bfloat16 g_Benc2[(size_t)NE * KBE];
__device__ __nv_bfloat16 g_Bdec2[(size_t)ND * KBD];
__device__ __nv_bfloat16 g_xenc2[(size_t)128 * B_ * 256];
__device__ __nv_bfloat16 g_ftp2[(size_t)32 * B_ * 128];
__device__ __nv_bfloat16 g_hP2[2][(size_t)B_ * 2048];        // parity, hi|lo
__device__ float         g_h[2][(size_t)B_ * H_];
__device__ float         g_Wc[(size_t)3072 * H_];
__device__ float         g_wob[3072];

__device__ __forceinline__ __nv_bfloat16 split_val(float w, bool lo) {
    __nv_bfloat16 hi = __float2bfloat16(w);
    if (!lo) return hi;
    return __float2bfloat16(w - __bfloat162float(hi));
}

// ------------------------------ precompute ---------------------------------
__global__ void k_wc(const float* __restrict__ Wi, const float* __restrict__ Wd) {
    int idx = blockIdx.x * 256 + threadIdx.x;          // exact 3072*1024
    int n = idx >> 10, k = idx & 1023;
    const float* wrow = Wi + n * 128 + 64;
    float s = 0.f;
#pragma unroll 8
    for (int o = 0; o < 64; o++) s += wrow[o] * Wd[o * 1024 + k];
    g_Wc[idx] = s;
}

__global__ void k_wob(const float* __restrict__ Wi, const float* __restrict__ bd) {
    int n = blockIdx.x * 256 + threadIdx.x;
    if (n >= 3072) return;
    float s = 0.f;
#pragma unroll 8
    for (int o = 0; o < 64; o++) s += Wi[n * 128 + 64 + o] * bd[o];
    g_wob[n] = s;
}

// Benc2 rows: [0,1024)=r ; [1024,2048)=z ; [2048,3072)=n_h ; [3072,4096)=n_i
// cols: [0,1024) W-hi | [1024,2048) W-lo | [2048,2176) Wi-hi | [2176,2304) Wi-lo
__global__ void build_benc2(const float* __restrict__ Wi, const float* __restrict__ Wh) {
    size_t idx = (size_t)blockIdx.x * 256 + threadIdx.x;   // exact NE*KBE
    int p = (int)(idx / KBE);
    int c = (int)(idx - (size_t)p * KBE);
    float w = 0.f; bool lo = false;
    if (c < 2048) {
        int cc = c & 1023; lo = (c >= 1024);
        if (p < 3072) w = Wh[(size_t)p * 1024 + cc];
    } else {
        int q = c - 2048; lo = (q >= 128); q &= 127;
        if (p < 2048)       w = Wi[p * 128 + q];
        else if (p >= 3072) w = Wi[(p - 1024) * 128 + q];
    }
    g_Benc2[idx] = split_val(w, lo);
}

// Bdec2 rows: [0,2048)=r,z (Wh+Wc) ; [2048,3072)=n_h (Wh) ; [3072,4096)=n_i (Wc)
//             [4096,4160)=Wd ; rest 0.
// cols: [0,1024) W-hi | [1024,2048) W-lo | [2048,2112) Wi-hi | [2112,2176) Wi-lo
__global__ void build_bdec2(const float* __restrict__ Wi, const float* __restrict__ Wh,
                            const float* __restrict__ Wd) {
    size_t idx = (size_t)blockIdx.x * 256 + threadIdx.x;   // exact ND*KBD
    int p = (int)(idx / KBD);
    int c = (int)(idx - (size_t)p * KBD);
    float w = 0.f; bool lo = false;
    if (c < 2048) {
        int cc = c & 1023; lo = (c >= 1024);
        if (p < 2048)      w = Wh[(size_t)p * 1024 + cc] + g_Wc[(size_t)p * 1024 + cc];
        else if (p < 3072) w = Wh[(size_t)p * 1024 + cc];
        else if (p < 4096) w = g_Wc[(size_t)(p - 1024) * 1024 + cc];
        else if (p < 4160) w = Wd[(size_t)(p - 4096) * 1024 + cc];
    } else {
        int q = c - 2048; lo = (q >= 64); q &= 63;
        if (p < 2048)                      w = Wi[p * 128 + q];
        else if (p >= 3072 && p < 4096)    w = Wi[(p - 1024) * 128 + q];
    }
    g_Bdec2[idx] = split_val(w, lo);
}

// xenc2[t][m][c]: c<128 hi of x, c>=128 lo ; x = [prior_t | labels_t]
__global__ void k_xenc2(const float* __restrict__ feats, const float* __restrict__ labels) {
    size_t idx = (size_t)blockIdx.x * 256 + threadIdx.x;   // exact 128*B_*256
    int t = (int)(idx / ((size_t)B_ * 256));
    int rem = (int)(idx - (size_t)t * B_ * 256);
    int m = rem >> 8;
    int c = rem & 255;
    int kk = c & 127;
    float v = (kk < 64) ? feats[((size_t)m * 159 + t) * 64 + kk]
                        : labels[((size_t)m * 128 + t) * 64 + (kk - 64)];
    g_xenc2[idx] = split_val(v, c >= 128);
}

// ftp2[j][m][c]: c<64 hi, c>=64 lo ; slot 31 zero
__global__ void k_ftp2(const float* __restrict__ feats) {
    size_t idx = (size_t)blockIdx.x * 256 + threadIdx.x;   // exact 32*B_*128
    int j = (int)(idx / ((size_t)B_ * 128));
    int rem = (int)(idx - (size_t)j * B_ * 128);
    int m = rem >> 7;
    int c = rem & 127;
    float v = (j == 31) ? 0.f : feats[((size_t)m * 159 + 128 + j) * 64 + (c & 63)];
    g_ftp2[idx] = split_val(v, c >= 64);
}

__global__ void init_h() {
    int idx = blockIdx.x * 256 + threadIdx.x;              // exact B_*2048
    g_hP2[0][idx] = __float2bfloat16(0.f);
    if (idx < B_ * H_) g_h[0][idx] = 0.f;
}

// --------------------------- mma helpers -----------------------------------
__device__ __forceinline__ void ldsm4(unsigned& r0, unsigned& r1, unsigned& r2,
                                      unsigned& r3, const void* p) {
    unsigned a = (unsigned)__cvta_generic_to_shared(p);
    asm volatile("ldmatrix.sync.aligned.m8n8.x4.shared.b16 {%0,%1,%2,%3},[%4];"
                 : "=r"(r0), "=r"(r1), "=r"(r2), "=r"(r3) : "r"(a));
}

__device__ __forceinline__ void mma16816(float* c, const unsigned* a,
                                         unsigned b0, unsigned b1) {
    asm volatile(
        "mma.sync.aligned.m16n8k16.row.col.f32.bf16.bf16.f32 "
        "{%0,%1,%2,%3},{%4,%5,%6,%7},{%8,%9},{%0,%1,%2,%3};"
        : "+f"(c[0]), "+f"(c[1]), "+f"(c[2]), "+f"(c[3])
        : "r"(a[0]), "r"(a[1]), "r"(a[2]), "r"(a[3]), "r"(b0), "r"(b1));
}

__device__ __forceinline__ void cpa16(uint32_t dst, const void* src) {
    asm volatile("cp.async.cg.shared.global [%0], [%1], 16;" :: "r"(dst), "l"(src));
}
#define CP_COMMIT() asm volatile("cp.async.commit_group;" ::: "memory")
#define CP_WAIT2()  asm volatile("cp.async.wait_group 2;" ::: "memory")

// ------------------------------ fused step ---------------------------------
// Gate CTA: 64(M) x 64(N-per-gate). Encoder: 3 B strips (r, z, nh|ni shared —
// target acc chosen by uniform branch with CONSTANT indices). Decoder: 4
// strips. Epilogue does GRU pointwise in registers. ps CTA (cid>=128, decoder
// only): Wd readout. Stage: A 64x144B + B 256x144B = 46080B; 4-stage ring.
#define KC     64
#define ROWB   144
#define STGB   46080
#define SMEMD  (4 * STGB)

template <int MODE>
__global__ __launch_bounds__(256)
void gru_step(int step, int parity, int base,
              const float* __restrict__ bi, const float* __restrict__ bh,
              const float* __restrict__ bd, float* __restrict__ out) {
    extern __shared__ char dsm[];
    const int cid = blockIdx.x + base;
    const int tid = threadIdx.x, lane = tid & 31, wid = tid >> 5;
    const uint32_t sb = (unsigned)__cvta_generic_to_shared(dsm);
    const int wm = (wid & 1) * 32;       // 2 warps over M (64)
    const int wn = (wid >> 1) * 16;      // 4 warps over N (64)
    const int grp = lane >> 2, tig = lane & 3;
    const int KB = MODE ? KBD : KBE;
    const __nv_bfloat16* Bmat = MODE ? g_Bdec2 : g_Benc2;
    const __nv_bfloat16* A2 = MODE ? g_ftp2 + (size_t)step * B_ * 128
                                   : g_xenc2 + (size_t)step * B_ * 256;
    const int lda2 = MODE ? 128 : 256;
    constexpr int NCH = MODE ? 51 : 54;
    const __nv_bfloat16* hPrd = g_hP2[parity];

    // ---------------- ps readout tile (decoder only) ----------------
    if (MODE == 1 && cid >= 128) {
        const int m0 = (cid - 128) * 64;
        auto FILLP = [&](int f) {
            int kb = f * KC;
            uint32_t bbase = sb + (f & 3) * STGB;
            const __nv_bfloat16* asrc; int lda, kc;
            if (kb < 2048)      { asrc = hPrd; lda = 2048; kc = kb; }
            else if (kb < 3072) { asrc = hPrd; lda = 2048; kc = kb - 2048; }
            else { asrc = A2; lda = lda2; kc = (kb < 3200) ? kb - 3072 : kb - 3200; }
            int bc = (kb < 1024) ? kb : ((kb < 3136) ? kb - 1024 : kb - 1088);
#pragma unroll
            for (int it = 0; it < 4; it++) {
                int ch = tid + it * 256;
                int row = (ch & 511) >> 3, seg = ch & 7;
                if (ch < 512)
                    cpa16(bbase + row * ROWB + seg * 16,
                          (const char*)(asrc + (size_t)(m0 + row) * lda + kc) + seg * 16);
                else
                    cpa16(bbase + 9216 + row * ROWB + seg * 16,
                          (const char*)(Bmat + (size_t)(4096 + row) * KB + bc) + seg * 16);
            }
            CP_COMMIT();
        };
        float acc[2][2][4];
#pragma unroll
        for (int mi = 0; mi < 2; mi++)
#pragma unroll
            for (int nj = 0; nj < 2; nj++)
#pragma unroll
                for (int q = 0; q < 4; q++) acc[mi][nj][q] = 0.f;
        FILLP(0); FILLP(1); FILLP(2);
        for (int i = 0; i < NCH; i++) {
            CP_WAIT2();
            __syncthreads();
            __nv_bfloat16* As = (__nv_bfloat16*)(dsm + (i & 3) * STGB);
            __nv_bfloat16* Bs = As + 64 * 72;
#pragma unroll
            for (int kh = 0; kh < 64; kh += 16) {
                unsigned a[2][4], b[4];
#pragma unroll
                for (int mi = 0; mi < 2; mi++)
                    ldsm4(a[mi][0], a[mi][1], a[mi][2], a[mi][3],
                          As + (wm + mi * 16 + (lane & 15)) * 72 + kh + (lane >> 4) * 8);
                ldsm4(b[0], b[1], b[2], b[3],
                      Bs + (wn + (lane & 15)) * 72 + kh + (lane >> 4) * 8);
#pragma unroll
                for (int mi = 0; mi < 2; mi++)
#pragma unroll
                    for (int nj = 0; nj < 2; nj++)
                        mma16816(acc[mi][nj], a[mi], b[nj], b[nj + 2]);
            }
            int f = i + 3;
            if (f < NCH) FILLP(f); else CP_COMMIT();
        }
#pragma unroll
        for (int mi = 0; mi < 2; mi++)
#pragma unroll
            for (int half = 0; half < 2; half++) {
                int row = m0 + wm + mi * 16 + grp + half * 8;
#pragma unroll
                for (int nj = 0; nj < 2; nj++) {
                    int col = wn + nj * 8 + tig * 2;
                    float2 v;
                    v.x = acc[mi][nj][half * 2 + 0] + bd[col];
                    v.y = acc[mi][nj][half * 2 + 1] + bd[col + 1];
                    *(float2*)&out[(size_t)row * 64 + col] = v;
                }
            }
        return;
    }

    // ---------------- gate tile ----------------
    const int ncol = cid & 15;
    const int m0 = (cid >> 4) * 64;
    constexpr int NS = MODE ? 4 : 3;
    constexpr int ITERS = MODE ? 10 : 8;

    auto FILL = [&](int f) {
        int kb = f * KC;
        uint32_t bbase = sb + (f & 3) * STGB;
        const __nv_bfloat16* asrc; int lda, kc;
        if (kb < 2048)      { asrc = hPrd; lda = 2048; kc = kb; }
        else if (kb < 3072) { asrc = hPrd; lda = 2048; kc = kb - 2048; }
        else {
            asrc = A2; lda = lda2;
            if (MODE == 0) kc = (kb < 3328) ? kb - 3072 : kb - 3328;
            else           kc = (kb < 3200) ? kb - 3072 : kb - 3200;
        }
        int bc;
        if (MODE == 0) bc = (kb < 1024) ? kb : ((kb < 3200) ? kb - 1024 : kb - 1152);
        else           bc = (kb < 1024) ? kb : ((kb < 3136) ? kb - 1024 : kb - 1088);
        const int rb2 = MODE ? 2048 : ((kb < 3072) ? 2048 : 3072);
#pragma unroll
        for (int it = 0; it < ITERS; it++) {
            int ch = tid + it * 256;
            if (ch < 512) {
                int row = ch >> 3, seg = ch & 7;
                cpa16(bbase + row * ROWB + seg * 16,
                      (const char*)(asrc + (size_t)(m0 + row) * lda + kc) + seg * 16);
            } else {
                int g = ch - 512;
                int brow = g >> 3, seg = g & 7;
                int s = brow >> 6, r = brow & 63;
                int p;
                if (s == 0)      p = ncol * 64 + r;
                else if (s == 1) p = 1024 + ncol * 64 + r;
                else if (s == 2) p = rb2 + ncol * 64 + r;
                else             p = 3072 + ncol * 64 + r;        // decoder n_i
                cpa16(bbase + 9216 + brow * ROWB + seg * 16,
                      (const char*)(Bmat + (size_t)p * KB + bc) + seg * 16);
            }
        }
        CP_COMMIT();
    };

    float acc[4][2][2][4];
#pragma unroll
    for (int g = 0; g < 4; g++)
#pragma unroll
        for (int mi = 0; mi < 2; mi++)
#pragma unroll
            for (int nj = 0; nj < 2; nj++)
#pragma unroll
                for (int q = 0; q < 4; q++) acc[g][mi][nj][q] = 0.f;

    FILL(0); FILL(1); FILL(2);

    for (int i = 0; i < NCH; i++) {
        CP_WAIT2();
        __syncthreads();
        __nv_bfloat16* As = (__nv_bfloat16*)(dsm + (i & 3) * STGB);
        __nv_bfloat16* Bs = As + 64 * 72;
        const bool late = (MODE == 0) && (i * KC >= 3072);

#pragma unroll
        for (int kh = 0; kh < 64; kh += 16) {
            unsigned a[2][4], b[NS][4];
#pragma unroll
            for (int mi = 0; mi < 2; mi++)
                ldsm4(a[mi][0], a[mi][1], a[mi][2], a[mi][3],
                      As + (wm + mi * 16 + (lane & 15)) * 72 + kh + (lane >> 4) * 8);
#pragma unroll
            for (int s = 0; s < NS; s++)
                ldsm4(b[s][0], b[s][1], b[s][2], b[s][3],
                      Bs + (s * 64 + wn + (lane & 15)) * 72 + kh + (lane >> 4) * 8);
#pragma unroll
            for (int mi = 0; mi < 2; mi++)
#pragma unroll
                for (int nj = 0; nj < 2; nj++) {
                    mma16816(acc[0][mi][nj], a[mi], b[0][nj], b[0][nj + 2]);
                    mma16816(acc[1][mi][nj], a[mi], b[1][nj], b[1][nj + 2]);
                    if (MODE == 1) {
                        mma16816(acc[2][mi][nj], a[mi], b[2][nj], b[2][nj + 2]);
                        mma16816(acc[3][mi][nj], a[mi], b[NS - 1][nj], b[NS - 1][nj + 2]);
                    } else {
                        if (!late) mma16816(acc[2][mi][nj], a[mi], b[2][nj], b[2][nj + 2]);
                        else       mma16816(acc[3][mi][nj], a[mi], b[2][nj], b[2][nj + 2]);
                    }
                }
        }
        int f = i + 3;
        if (f < NCH) FILL(f); else CP_COMMIT();
    }

    // ------------------------------ epilogue -------------------------------
    const int pw = parity ^ 1;
    const float* hr = g_h[parity];
    float* hw = g_h[pw];
    __nv_bfloat16* hPw = g_hP2[pw];

#pragma unroll
    for (int mi = 0; mi < 2; mi++)
#pragma unroll
        for (int half = 0; half < 2; half++) {
            int row = m0 + wm + mi * 16 + grp + half * 8;
#pragma unroll
            for (int nj = 0; nj < 2; nj++) {
#pragma unroll
                for (int c = 0; c < 2; c++) {
                    int coln = wn + nj * 8 + tig * 2 + c;
                    int n = ncol * 64 + coln;
                    int q = half * 2 + c;
                    float wr = MODE ? g_wob[n] : 0.f;
                    float wz = MODE ? g_wob[1024 + n] : 0.f;
                    float wn_ = MODE ? g_wob[2048 + n] : 0.f;
                    float r = acc[0][mi][nj][q] + bi[n] + bh[n] + wr;
                    float z = acc[1][mi][nj][q] + bi[1024 + n] + bh[1024 + n] + wz;
                    float ghn = acc[2][mi][nj][q] + bh[2048 + n];
                    float gin = acc[3][mi][nj][q] + bi[2048 + n] + wn_;
                    r = 1.f / (1.f + __expf(-r));
                    z = 1.f / (1.f + __expf(-z));
                    float nn = tanhf(gin + r * ghn);
                    float ho = hr[(size_t)row * 1024 + n];
                    float h = (1.f - z) * nn + z * ho;
                    hw[(size_t)row * 1024 + n] = h;
                    __nv_bfloat16 hi = __float2bfloat16(h);
                    __nv_bfloat16 lo = __float2bfloat16(h - __bfloat162float(hi));
                    hPw[(size_t)row * 2048 + n] = hi;
                    hPw[(size_t)row * 2048 + 1024 + n] = lo;
                }
            }
        }
}

// ------------------------------- launch ------------------------------------
extern "C" void kernel_launch(void* const* d_in, const int* in_sizes, int n_in,
                              void* d_out, int out_size) {
    const float* feats  = (const float*)d_in[0];
    const float* labels = (const float*)d_in[1];
    const float* Wi     = (const float*)d_in[2];
    const float* Wh     = (const float*)d_in[3];
    const float* bi     = (const float*)d_in[4];
    const float* bh     = (const float*)d_in[5];
    const float* Wd     = (const float*)d_in[6];
    const float* bd     = (const float*)d_in[7];
    float* out = (float*)d_out;

    cudaFuncSetAttribute(gru_step<0>, cudaFuncAttributeMaxDynamicSharedMemorySize, SMEMD);
    cudaFuncSetAttribute(gru_step<1>, cudaFuncAttributeMaxDynamicSharedMemorySize, SMEMD);

    k_wc<<<12288, 256>>>(Wi, Wd);
    k_wob<<<12, 256>>>(Wi, bd);
    build_benc2<<<(int)(((size_t)NE * KBE) / 256), 256>>>(Wi, Wh);
    build_bdec2<<<(int)(((size_t)ND * KBD) / 256), 256>>>(Wi, Wh, Wd);
    k_xenc2<<<(int)(((size_t)128 * B_ * 256) / 256), 256>>>(feats, labels);
    k_ftp2<<<(int)(((size_t)32 * B_ * 128) / 256), 256>>>(feats);
    init_h<<<(B_ * 2048) / 256, 256>>>();

    for (int t = 0; t < 128; t++)
        gru_step<0><<<128, 256, SMEMD>>>(t, t & 1, 0, bi, bh, bd, out);
    for (int j = 0; j < 31; j++)
        gru_step<1><<<136, 256, SMEMD>>>(j, j & 1, 0, bi, bh, bd,
                                         out + (size_t)j * B_ * 64);
    gru_step<1><<<8, 256, SMEMD>>>(31, 1, 128, bi, bh, bd,
                                   out + (size_t)31 * B_ * 64);
}

// round 17
// speedup vs baseline: 4.6854x; 1.2086x over previous
#include <cuda_runtime.h>
#include <cuda_bf16.h>
#include <cstdint>

#define B_    512
#define H_    1024
#define LDG   4352
#define NE    4096
#define ND    4352
#define KBE   2304      // Benc2 physical cols: Whi|Wlo|Wi_hi(128)|Wi_lo(128)
#define KBD   2176      // Bdec2 physical cols: Whi|Wlo|Wi_hi(64)|Wi_lo(64)

// ----------------------- device scratch (no allocs) ------------------------
__device__ __nv_bfloat16 g_Benc2[(size_t)NE * KBE];
__device__ __nv_bfloat16 g_Bdec2[(size_t)ND * KBD];
__device__ __nv_bfloat16 g_xenc2[(size_t)128 * B_ * 256];
__device__ __nv_bfloat16 g_ftp2[(size_t)32 * B_ * 128];
__device__ __nv_bfloat16 g_hP2[(size_t)B_ * 2048];           // hi|lo
__device__ float         g_h[(size_t)B_ * H_];
__device__ float         g_G[(size_t)B_ * LDG];
__device__ float         g_G2[(size_t)B_ * 3072];            // split-K partials
__device__ float         g_Wc[(size_t)3072 * H_];
__device__ float         g_wob[3072];

__device__ __forceinline__ __nv_bfloat16 split_val(float w, bool lo) {
    __nv_bfloat16 hi = __float2bfloat16(w);
    if (!lo) return hi;
    return __float2bfloat16(w - __bfloat162float(hi));
}

// ------------------------------ precompute ---------------------------------
__global__ void k_wc(const float* __restrict__ Wi, const float* __restrict__ Wd) {
    int idx = blockIdx.x * 256 + threadIdx.x;          // exact 3072*1024
    int n = idx >> 10, k = idx & 1023;
    const float* wrow = Wi + n * 128 + 64;
    float s = 0.f;
#pragma unroll 8
    for (int o = 0; o < 64; o++) s += wrow[o] * Wd[o * 1024 + k];
    g_Wc[idx] = s;
}

__global__ void k_wob(const float* __restrict__ Wi, const float* __restrict__ bd) {
    int n = blockIdx.x * 256 + threadIdx.x;
    if (n >= 3072) return;
    float s = 0.f;
#pragma unroll 8
    for (int o = 0; o < 64; o++) s += Wi[n * 128 + 64 + o] * bd[o];
    g_wob[n] = s;
}

// Benc2 rows: [0,2048)=r,z ; [2048,3072)=n_h ; [3072,4096)=n_i (Wi rows p-1024)
__global__ void build_benc2(const float* __restrict__ Wi, const float* __restrict__ Wh) {
    size_t idx = (size_t)blockIdx.x * 256 + threadIdx.x;   // exact NE*KBE
    int p = (int)(idx / KBE);
    int c = (int)(idx - (size_t)p * KBE);
    float w = 0.f; bool lo = false;
    if (c < 2048) {
        int cc = c & 1023; lo = (c >= 1024);
        if (p < 3072) w = Wh[(size_t)p * 1024 + cc];
    } else {
        int q = c - 2048; lo = (q >= 128); q &= 127;
        if (p < 2048)       w = Wi[p * 128 + q];
        else if (p >= 3072) w = Wi[(p - 1024) * 128 + q];
    }
    g_Benc2[idx] = split_val(w, lo);
}

__global__ void build_bdec2(const float* __restrict__ Wi, const float* __restrict__ Wh,
                            const float* __restrict__ Wd) {
    size_t idx = (size_t)blockIdx.x * 256 + threadIdx.x;   // exact ND*KBD
    int p = (int)(idx / KBD);
    int c = (int)(idx - (size_t)p * KBD);
    float w = 0.f; bool lo = false;
    if (c < 2048) {
        int cc = c & 1023; lo = (c >= 1024);
        if (p < 2048)      w = Wh[(size_t)p * 1024 + cc] + g_Wc[(size_t)p * 1024 + cc];
        else if (p < 3072) w = Wh[(size_t)p * 1024 + cc];
        else if (p < 4096) w = g_Wc[(size_t)(p - 1024) * 1024 + cc];
        else if (p < 4160) w = Wd[(size_t)(p - 4096) * 1024 + cc];
    } else {
        int q = c - 2048; lo = (q >= 64); q &= 63;
        if (p < 2048)                      w = Wi[p * 128 + q];
        else if (p >= 3072 && p < 4096)    w = Wi[(p - 1024) * 128 + q];
    }
    g_Bdec2[idx] = split_val(w, lo);
}

__global__ void k_xenc2(const float* __restrict__ feats, const float* __restrict__ labels) {
    size_t idx = (size_t)blockIdx.x * 256 + threadIdx.x;   // exact 128*B_*256
    int t = (int)(idx / ((size_t)B_ * 256));
    int rem = (int)(idx - (size_t)t * B_ * 256);
    int m = rem >> 8;
    int c = rem & 255;
    int kk = c & 127;
    float v = (kk < 64) ? feats[((size_t)m * 159 + t) * 64 + kk]
                        : labels[((size_t)m * 128 + t) * 64 + (kk - 64)];
    g_xenc2[idx] = split_val(v, c >= 128);
}

__global__ void k_ftp2(const float* __restrict__ feats) {
    size_t idx = (size_t)blockIdx.x * 256 + threadIdx.x;   // exact 32*B_*128
    int j = (int)(idx / ((size_t)B_ * 128));
    int rem = (int)(idx - (size_t)j * B_ * 128);
    int m = rem >> 7;
    int c = rem & 127;
    float v = (j == 31) ? 0.f : feats[((size_t)m * 159 + 128 + j) * 64 + (c & 63)];
    g_ftp2[idx] = split_val(v, c >= 64);
}

__global__ void init_h() {
    int idx = blockIdx.x * 256 + threadIdx.x;              // exact B_*2048
    g_hP2[idx] = __float2bfloat16(0.f);
    if (idx < B_ * H_) g_h[idx] = 0.f;
}

// --------------------------- mma helpers -----------------------------------
__device__ __forceinline__ void ldsm4(unsigned& r0, unsigned& r1, unsigned& r2,
                                      unsigned& r3, const void* p) {
    unsigned a = (unsigned)__cvta_generic_to_shared(p);
    asm volatile("ldmatrix.sync.aligned.m8n8.x4.shared.b16 {%0,%1,%2,%3},[%4];"
                 : "=r"(r0), "=r"(r1), "=r"(r2), "=r"(r3) : "r"(a));
}

__device__ __forceinline__ void mma16816(float* c, const unsigned* a,
                                         unsigned b0, unsigned b1) {
    asm volatile(
        "mma.sync.aligned.m16n8k16.row.col.f32.bf16.bf16.f32 "
        "{%0,%1,%2,%3},{%4,%5,%6,%7},{%8,%9},{%0,%1,%2,%3};"
        : "+f"(c[0]), "+f"(c[1]), "+f"(c[2]), "+f"(c[3])
        : "r"(a[0]), "r"(a[1]), "r"(a[2]), "r"(a[3]), "r"(b0), "r"(b1));
}

__device__ __forceinline__ void cpa16(uint32_t dst, const void* src) {
    asm volatile("cp.async.cg.shared.global [%0], [%1], 16;" :: "r"(dst), "l"(src));
}
#define CP_COMMIT() asm volatile("cp.async.commit_group;" ::: "memory")
#define CP_WAIT2()  asm volatile("cp.async.wait_group 2;" ::: "memory")

// 128x128 tile pipeline constants (R9-proven)
#define KC     64
#define ROWB   144
#define STGB   36864
#define SMEMD  (4 * STGB)

// -------------------- balanced encoder GEMM (36 chunks/CTA) ----------------
// Per mtile, 36 CTAs x exactly 36 chunks:
//  r<16 : rz tile t=r, k[0,36)                     -> G   col t*128
//  r<24 : rz tails: tile 2b k[36,54) + 2b+1 same   -> G2  (b=r-16)
//  r<32 : nh tile u=r-24, k[0,36)                  -> G   col 2048+u*128
//  r>=32: nh tails 2d,2d+1 k[36,48) -> G2 ; ni 2d,2d+1 k[48,54) -> G (d=r-32)
__global__ __launch_bounds__(256)
void enc_bal(int step, const float* __restrict__ bi) {
    extern __shared__ char dsm[];
    const int r = blockIdx.x;            // 0..35
    const int m0 = blockIdx.y * 128;
    const int tid = threadIdx.x, lane = tid & 31, wid = tid >> 5;
    const uint32_t sb = (unsigned)__cvta_generic_to_shared(dsm);
    const int wm = (wid & 3) * 32, wn = (wid >> 2) * 64;
    const int grp = lane >> 2, tig = lane & 3;
    const __nv_bfloat16* A2 = g_xenc2 + (size_t)step * B_ * 256;

    // ---- part table (uniform per CTA): ends, col bases, dst select ----
    int pe0 = 99, pe1 = 99, pe2 = 99, pe3 = 99;
    int cb0 = 0, cb1 = 0, cb2 = 0, cb3 = 0;
    int d0 = 0, d1 = 0, d2 = 0, d3 = 0;   // 0 = G, 1 = G2
    if (r < 16)      { pe0 = 35; cb0 = r * 128; }
    else if (r < 24) { int b = r - 16;
                       pe0 = 17; cb0 = (2*b) * 128;     d0 = 1;
                       pe1 = 35; cb1 = (2*b+1) * 128;   d1 = 1; }
    else if (r < 32) { pe0 = 35; cb0 = 2048 + (r-24) * 128; }
    else             { int d = r - 32;
                       pe0 = 11; cb0 = 2048 + (2*d) * 128;   d0 = 1;
                       pe1 = 23; cb1 = 2048 + (2*d+1) * 128; d1 = 1;
                       pe2 = 29; cb2 = 3072 + (2*d) * 128;
                       pe3 = 35; cb3 = 3072 + (2*d+1) * 128; }

    // chunk f -> (kb, tile row base)
    auto MAP = [&](int f, int& kb, int& trb) {
        if (r < 16)      { kb = f * 64; trb = r * 128; }
        else if (r < 24) { int b = r - 16;
                           if (f < 18) { kb = (36 + f) * 64; trb = (2*b) * 128; }
                           else        { kb = (18 + f) * 64; trb = (2*b+1) * 128; } }
        else if (r < 32) { kb = f * 64; trb = 2048 + (r-24) * 128; }
        else             { int d = r - 32;
                           if (f < 12)      { kb = (36 + f) * 64; trb = 2048 + (2*d) * 128; }
                           else if (f < 24) { kb = (24 + f) * 64; trb = 2048 + (2*d+1) * 128; }
                           else if (f < 30) { kb = (24 + f) * 64; trb = 3072 + (2*d) * 128; }
                           else             { kb = (18 + f) * 64; trb = 3072 + (2*d+1) * 128; } }
    };

    auto FILL = [&](int f) {
        int kb, trb; MAP(f, kb, trb);
        uint32_t base = sb + (f & 3) * STGB;
        const __nv_bfloat16* asrc; int lda, kc;
        if (kb < 2048)      { asrc = g_hP2; lda = 2048; kc = kb; }
        else if (kb < 3072) { asrc = g_hP2; lda = 2048; kc = kb - 2048; }
        else                { asrc = A2; lda = 256; kc = (kb < 3328) ? kb - 3072 : kb - 3328; }
        int bc = (kb < 1024) ? kb : ((kb < 3200) ? kb - 1024 : kb - 1152);
#pragma unroll
        for (int it = 0; it < 8; it++) {
            int ch = tid + it * 256;
            int isB = ch >= 1024;
            int g = ch & 1023;
            int row = g >> 3, seg = g & 7;
            const char* src;
            uint32_t dst = base + (isB ? (128 * ROWB) : 0) + row * ROWB + seg * 16;
            if (!isB)
                src = (const char*)(asrc + (size_t)(m0 + row) * lda + kc) + seg * 16;
            else
                src = (const char*)(g_Benc2 + (size_t)(trb + row) * KBE + bc) + seg * 16;
            cpa16(dst, src);
        }
        CP_COMMIT();
    };

    float acc[2][8][4];
#pragma unroll
    for (int i = 0; i < 2; i++)
#pragma unroll
        for (int j = 0; j < 8; j++)
#pragma unroll
            for (int q = 0; q < 4; q++) acc[i][j][q] = 0.f;

    auto STORE = [&](int colbase, int dsel) {
        float* dst = dsel ? g_G2 : g_G;
        int ld = dsel ? 3072 : LDG;
#pragma unroll
        for (int mi = 0; mi < 2; mi++)
#pragma unroll
            for (int nj = 0; nj < 8; nj++) {
                int row = m0 + wm + mi * 16 + grp;
                int col = colbase + wn + nj * 8 + tig * 2;
                *(float2*)&dst[(size_t)row * ld + col] =
                    make_float2(acc[mi][nj][0], acc[mi][nj][1]);
                *(float2*)&dst[(size_t)(row + 8) * ld + col] =
                    make_float2(acc[mi][nj][2], acc[mi][nj][3]);
                acc[mi][nj][0] = 0.f; acc[mi][nj][1] = 0.f;
                acc[mi][nj][2] = 0.f; acc[mi][nj][3] = 0.f;
            }
    };

    FILL(0); FILL(1); FILL(2);

    for (int i = 0; i < 36; i++) {
        CP_WAIT2();
        __syncthreads();
        __nv_bfloat16* As = (__nv_bfloat16*)(dsm + (i & 3) * STGB);
        __nv_bfloat16* Bs = As + 128 * 72;
#pragma unroll
        for (int kh = 0; kh < 64; kh += 16) {
            unsigned a[2][4], b[4][4];
#pragma unroll
            for (int mi = 0; mi < 2; mi++)
                ldsm4(a[mi][0], a[mi][1], a[mi][2], a[mi][3],
                      As + (wm + mi * 16 + (lane & 15)) * 72 + kh + (lane >> 4) * 8);
#pragma unroll
            for (int np = 0; np < 4; np++)
                ldsm4(b[np][0], b[np][1], b[np][2], b[np][3],
                      Bs + (wn + np * 16 + (lane & 15)) * 72 + kh + (lane >> 4) * 8);
#pragma unroll
            for (int mi = 0; mi < 2; mi++)
#pragma unroll
                for (int nj = 0; nj < 8; nj++) {
                    int np = nj >> 1;
                    unsigned b0 = (nj & 1) ? b[np][1] : b[np][0];
                    unsigned b1 = (nj & 1) ? b[np][3] : b[np][2];
                    mma16816(acc[mi][nj], a[mi], b0, b1);
                }
        }
        int f = i + 3;
        if (f < 36) FILL(f); else CP_COMMIT();

        if (i == pe0)      STORE(cb0, d0);
        else if (i == pe1) STORE(cb1, d1);
        else if (i == pe2) STORE(cb2, d2);
        else if (i == pe3) STORE(cb3, d3);
    }
}

// ---------------------------- decoder GEMM (R9) -----------------------------
__global__ __launch_bounds__(256)
void dec_gemm(int step) {
    extern __shared__ char dsm[];
    const int tid = threadIdx.x;
    const int lane = tid & 31, wid = tid >> 5;
    const int ntile = blockIdx.x;
    const int n0 = ntile * 128, m0 = blockIdx.y * 128;
    const int region = ntile >> 3;
    const int kend = (region == 2 || region >= 4) ? 3072 : 3264;
    const int nch = kend >> 6;
    const __nv_bfloat16* A2 = g_ftp2 + (size_t)step * B_ * 128;
    const uint32_t sb = (unsigned)__cvta_generic_to_shared(dsm);

    auto FILL = [&](int f) {
        int kb = f * KC;
        uint32_t base = sb + (f & 3) * STGB;
        const __nv_bfloat16* asrc; int lda, kc;
        if (kb < 2048)      { asrc = g_hP2; lda = 2048; kc = kb; }
        else if (kb < 3072) { asrc = g_hP2; lda = 2048; kc = kb - 2048; }
        else                { asrc = A2; lda = 128; kc = (kb < 3200) ? kb - 3072 : kb - 3200; }
        int bc = (kb < 1024) ? kb : ((kb < 3136) ? kb - 1024 : kb - 1088);
#pragma unroll
        for (int it = 0; it < 8; it++) {
            int ch = tid + it * 256;
            int isB = ch >= 1024;
            int g = ch & 1023;
            int row = g >> 3, seg = g & 7;
            const char* src;
            uint32_t dst = base + (isB ? (128 * ROWB) : 0) + row * ROWB + seg * 16;
            if (!isB)
                src = (const char*)(asrc + (size_t)(m0 + row) * lda + kc) + seg * 16;
            else
                src = (const char*)(g_Bdec2 + (size_t)(n0 + row) * KBD + bc) + seg * 16;
            cpa16(dst, src);
        }
        CP_COMMIT();
    };

    const int wm = (wid & 3) * 32, wn = (wid >> 2) * 64;
    const int grp = lane >> 2, tig = lane & 3;

    float acc[2][8][4];
#pragma unroll
    for (int i = 0; i < 2; i++)
#pragma unroll
        for (int j = 0; j < 8; j++)
#pragma unroll
            for (int q = 0; q < 4; q++) acc[i][j][q] = 0.f;

    FILL(0); FILL(1); FILL(2);

    for (int i = 0; i < nch; i++) {
        CP_WAIT2();
        __syncthreads();
        __nv_bfloat16* As = (__nv_bfloat16*)(dsm + (i & 3) * STGB);
        __nv_bfloat16* Bs = As + 128 * 72;
#pragma unroll
        for (int kh = 0; kh < 64; kh += 16) {
            unsigned a[2][4], b[4][4];
#pragma unroll
            for (int mi = 0; mi < 2; mi++)
                ldsm4(a[mi][0], a[mi][1], a[mi][2], a[mi][3],
                      As + (wm + mi * 16 + (lane & 15)) * 72 + kh + (lane >> 4) * 8);
#pragma unroll
            for (int np = 0; np < 4; np++)
                ldsm4(b[np][0], b[np][1], b[np][2], b[np][3],
                      Bs + (wn + np * 16 + (lane & 15)) * 72 + kh + (lane >> 4) * 8);
#pragma unroll
            for (int mi = 0; mi < 2; mi++)
#pragma unroll
                for (int nj = 0; nj < 8; nj++) {
                    int np = nj >> 1;
                    unsigned b0 = (nj & 1) ? b[np][1] : b[np][0];
                    unsigned b1 = (nj & 1) ? b[np][3] : b[np][2];
                    mma16816(acc[mi][nj], a[mi], b0, b1);
                }
        }
        int f = i + 3;
        if (f < nch) FILL(f); else CP_COMMIT();
    }

#pragma unroll
    for (int mi = 0; mi < 2; mi++)
#pragma unroll
        for (int nj = 0; nj < 8; nj++) {
            int row = m0 + wm + mi * 16 + grp;
            int col = n0 + wn + nj * 8 + tig * 2;
            *(float2*)&g_G[(size_t)row * LDG + col] =
                make_float2(acc[mi][nj][0], acc[mi][nj][1]);
            *(float2*)&g_G[(size_t)(row + 8) * LDG + col] =
                make_float2(acc[mi][nj][2], acc[mi][nj][3]);
        }
}

// ------------------------------ pointwise ----------------------------------
__global__ void pw_enc(const float* __restrict__ bi, const float* __restrict__ bh) {
    int idx = blockIdx.x * 256 + threadIdx.x;     // exact 512*1024
    int m = idx >> 10, n = idx & 1023;
    const float* Gr = g_G + (size_t)m * LDG;
    const float* G2r = g_G2 + (size_t)m * 3072;
    float r = Gr[n] + G2r[n] + bi[n] + bh[n];
    float z = Gr[1024 + n] + G2r[1024 + n] + bi[1024 + n] + bh[1024 + n];
    float ghn = Gr[2048 + n] + G2r[2048 + n] + bh[2048 + n];
    float gin = Gr[3072 + n] + bi[2048 + n];
    r = 1.f / (1.f + __expf(-r));
    z = 1.f / (1.f + __expf(-z));
    float nn = tanhf(gin + r * ghn);
    float ho = g_h[idx];
    float h = (1.f - z) * nn + z * ho;
    g_h[idx] = h;
    __nv_bfloat16 hi = __float2bfloat16(h);
    __nv_bfloat16 lo = __float2bfloat16(h - __bfloat162float(hi));
    g_hP2[(size_t)m * 2048 + n] = hi;
    g_hP2[(size_t)m * 2048 + 1024 + n] = lo;
}

// blocks [0,2048): gate math (skipped if !do_h). blocks [2048,2176): psout.
__global__ void pw_dec(int do_h, const float* __restrict__ bi,
                       const float* __restrict__ bh, const float* __restrict__ bd,
                       float* __restrict__ out) {
    int blk = blockIdx.x;
    if (blk >= 2048) {
        int idx = (blk - 2048) * 256 + threadIdx.x;   // exact 512*64
        int m = idx >> 6, o = idx & 63;
        out[idx] = g_G[(size_t)m * LDG + 4096 + o] + bd[o];
        return;
    }
    if (!do_h) return;
    int idx = blk * 256 + threadIdx.x;                // exact 512*1024
    int m = idx >> 10, n = idx & 1023;
    const float* Gr = g_G + (size_t)m * LDG;
    float r = Gr[n] + bi[n] + bh[n] + g_wob[n];
    float z = Gr[1024 + n] + bi[1024 + n] + bh[1024 + n] + g_wob[1024 + n];
    float ghn = Gr[2048 + n] + bh[2048 + n];
    float gin = Gr[3072 + n] + bi[2048 + n] + g_wob[2048 + n];
    r = 1.f / (1.f + __expf(-r));
    z = 1.f / (1.f + __expf(-z));
    float nn = tanhf(gin + r * ghn);
    float ho = g_h[idx];
    float h = (1.f - z) * nn + z * ho;
    g_h[idx] = h;
    __nv_bfloat16 hi = __float2bfloat16(h);
    __nv_bfloat16 lo = __float2bfloat16(h - __bfloat162float(hi));
    g_hP2[(size_t)m * 2048 + n] = hi;
    g_hP2[(size_t)m * 2048 + 1024 + n] = lo;
}

// ------------------------------- launch ------------------------------------
extern "C" void kernel_launch(void* const* d_in, const int* in_sizes, int n_in,
                              void* d_out, int out_size) {
    const float* feats  = (const float*)d_in[0];
    const float* labels = (const float*)d_in[1];
    const float* Wi     = (const float*)d_in[2];
    const float* Wh     = (const float*)d_in[3];
    const float* bi     = (const float*)d_in[4];
    const float* bh     = (const float*)d_in[5];
    const float* Wd     = (const float*)d_in[6];
    const float* bd     = (const float*)d_in[7];
    float* out = (float*)d_out;

    cudaFuncSetAttribute(enc_bal, cudaFuncAttributeMaxDynamicSharedMemorySize, SMEMD);
    cudaFuncSetAttribute(dec_gemm, cudaFuncAttributeMaxDynamicSharedMemorySize, SMEMD);

    k_wc<<<12288, 256>>>(Wi, Wd);
    k_wob<<<12, 256>>>(Wi, bd);
    build_benc2<<<(int)(((size_t)NE * KBE) / 256), 256>>>(Wi, Wh);
    build_bdec2<<<(int)(((size_t)ND * KBD) / 256), 256>>>(Wi, Wh, Wd);
    k_xenc2<<<(int)(((size_t)128 * B_ * 256) / 256), 256>>>(feats, labels);
    k_ftp2<<<(int)(((size_t)32 * B_ * 128) / 256), 256>>>(feats);
    init_h<<<(B_ * 2048) / 256, 256>>>();

    for (int t = 0; t < 128; t++) {
        enc_bal<<<dim3(36, 4), 256, SMEMD>>>(t, bi);
        pw_enc<<<2048, 256>>>(bi, bh);
    }
    for (int j = 0; j < 32; j++) {
        dec_gemm<<<dim3(34, 4), 256, SMEMD>>>(j);
        pw_dec<<<2176, 256>>>((j < 31) ? 1 : 0, bi, bh, bd,
                              out + (size_t)j * B_ * 64);
    }
}